// round 9
// baseline (speedup 1.0000x reference)
#include <cuda_runtime.h>
#include <math_constants.h>

// Problem constants
#define TAU_SYN_INV 0.5f
#define TAU_MEM_INV 0.5f
#define V_TH        1.0f
#define V_RESET     0.0f
#define INHIB      (-5.0f)

constexpr int N_COLS  = 8192;
constexpr int THREADS = 512;
constexpr int NVEC    = N_COLS / 4;            // 2048 float4 per row
constexpr int ITERS   = NVEC / THREADS;        // 4 float4 per thread per row
constexpr int NWARPS  = THREADS / 32;          // 16
constexpr int ROWS_PER_CTA = 2;

// (val, idx) argmax with first-index tie-break: prefer larger val, then smaller idx.
__device__ __forceinline__ void amax_update(float& bv, int& bi, float v, int i) {
    if (v > bv || (v == bv && i < bi)) { bv = v; bi = i; }
}

__global__ __launch_bounds__(THREADS, 2)
void lif_wta_kernel(const float4* __restrict__ x,
                    const float4* __restrict__ vmem,
                    const float4* __restrict__ isyn,
                    float4* __restrict__ z_out,
                    float4* __restrict__ v_out,
                    float4* __restrict__ i_out)
{
    const int tid = threadIdx.x;
    const size_t base0 = (size_t)(blockIdx.x * ROWS_PER_CTA + 0) * NVEC;
    const size_t base1 = (size_t)(blockIdx.x * ROWS_PER_CTA + 1) * NVEC;

    __shared__ float s_wval[ROWS_PER_CTA][NWARPS];
    __shared__ int   s_widx[ROWS_PER_CTA][NWARPS];
    __shared__ float s_best[ROWS_PER_CTA];
    __shared__ int   s_bidx[ROWS_PER_CTA];

    float best0 = -CUDART_INF_F, best1 = -CUDART_INF_F;
    int   bidx0 = N_COLS,        bidx1 = N_COLS;

    // ---- Phase 1: compute + stream z, i_new for both rows; local argmax per row ----
    #pragma unroll
    for (int it = 0; it < ITERS; it++) {
        const int c = tid + it * THREADS;
        {   // row 0
            const float4 xv = x[base0 + c];
            const float4 vv = vmem[base0 + c];
            const float4 iv = isyn[base0 + c];
            float4 in4, z4;
            const float* xp = (const float*)&xv;
            const float* vp = (const float*)&vv;
            const float* ip = (const float*)&iv;
            float* inp = (float*)&in4;
            float* zp  = (float*)&z4;
            #pragma unroll
            for (int j = 0; j < 4; j++) {
                const float i_new = ip[j] + TAU_SYN_INV * (xp[j] - ip[j]);
                const float v_new = vp[j] + TAU_MEM_INV * (i_new - vp[j]);
                const bool  spike = (v_new >= V_TH);
                inp[j] = i_new;
                zp[j]  = spike ? 1.0f : 0.0f;
                if (spike) amax_update(best0, bidx0, v_new, c * 4 + j);
            }
            i_out[base0 + c] = in4;
            z_out[base0 + c] = z4;
        }
        {   // row 1
            const float4 xv = x[base1 + c];
            const float4 vv = vmem[base1 + c];
            const float4 iv = isyn[base1 + c];
            float4 in4, z4;
            const float* xp = (const float*)&xv;
            const float* vp = (const float*)&vv;
            const float* ip = (const float*)&iv;
            float* inp = (float*)&in4;
            float* zp  = (float*)&z4;
            #pragma unroll
            for (int j = 0; j < 4; j++) {
                const float i_new = ip[j] + TAU_SYN_INV * (xp[j] - ip[j]);
                const float v_new = vp[j] + TAU_MEM_INV * (i_new - vp[j]);
                const bool  spike = (v_new >= V_TH);
                inp[j] = i_new;
                zp[j]  = spike ? 1.0f : 0.0f;
                if (spike) amax_update(best1, bidx1, v_new, c * 4 + j);
            }
            i_out[base1 + c] = in4;
            z_out[base1 + c] = z4;
        }
    }

    // ---- Warp reductions (both rows) ----
    #pragma unroll
    for (int off = 16; off > 0; off >>= 1) {
        const float o0 = __shfl_down_sync(0xFFFFFFFFu, best0, off);
        const int   i0 = __shfl_down_sync(0xFFFFFFFFu, bidx0, off);
        amax_update(best0, bidx0, o0, i0);
        const float o1 = __shfl_down_sync(0xFFFFFFFFu, best1, off);
        const int   i1 = __shfl_down_sync(0xFFFFFFFFu, bidx1, off);
        amax_update(best1, bidx1, o1, i1);
    }
    if ((tid & 31) == 0) {
        s_wval[0][tid >> 5] = best0;  s_widx[0][tid >> 5] = bidx0;
        s_wval[1][tid >> 5] = best1;  s_widx[1][tid >> 5] = bidx1;
    }
    __syncthreads();

    // ---- Final reductions: warp 0 -> row 0, warp 1 -> row 1 (parallel) ----
    if (tid < 64) {
        const int r = tid >> 5;            // warp id = row
        const int l = tid & 31;
        float fb = (l < NWARPS) ? s_wval[r][l] : -CUDART_INF_F;
        int   fi = (l < NWARPS) ? s_widx[r][l] : N_COLS;
        #pragma unroll
        for (int off = 16; off > 0; off >>= 1) {
            const float ov = __shfl_down_sync(0xFFFFFFFFu, fb, off);
            const int   oi = __shfl_down_sync(0xFFFFFFFFu, fi, off);
            amax_update(fb, fi, ov, oi);
        }
        if (l == 0) { s_best[r] = fb; s_bidx[r] = fi; }
    }
    __syncthreads();

    // ---- Phase 2: write v_out for both rows ----
    #pragma unroll
    for (int r = 0; r < ROWS_PER_CTA; r++) {
        const size_t base = (r == 0) ? base0 : base1;
        const bool any_spike = (s_best[r] > -CUDART_INF_F);   // block-uniform
        const int  winner    = s_bidx[r];

        if (any_spike) {
            // Winner-take-all row: winner gets V_RESET (it spiked), rest get INHIB.
            #pragma unroll
            for (int it = 0; it < ITERS; it++) {
                const int c = tid + it * THREADS;
                float4 o;
                o.x = INHIB; o.y = INHIB; o.z = INHIB; o.w = INHIB;
                const int b4 = c * 4;
                if (winner >= b4 && winner < b4 + 4) {
                    ((float*)&o)[winner - b4] = V_RESET;
                }
                v_out[base + c] = o;
            }
        } else {
            // No spikes in row (astronomically rare): recompute v_new (re-reads hit L2).
            #pragma unroll
            for (int it = 0; it < ITERS; it++) {
                const int c = tid + it * THREADS;
                const float4 xv = x[base + c];
                const float4 vv = vmem[base + c];
                const float4 iv = isyn[base + c];
                float4 o;
                const float* xp = (const float*)&xv;
                const float* vp = (const float*)&vv;
                const float* ip = (const float*)&iv;
                float* op = (float*)&o;
                #pragma unroll
                for (int j = 0; j < 4; j++) {
                    const float i_new = ip[j] + TAU_SYN_INV * (xp[j] - ip[j]);
                    op[j] = vp[j] + TAU_MEM_INV * (i_new - vp[j]);
                }
                v_out[base + c] = o;
            }
        }
    }
}

extern "C" void kernel_launch(void* const* d_in, const int* in_sizes, int n_in,
                              void* d_out, int out_size) {
    const float4* x = (const float4*)d_in[0];
    const float4* v = (const float4*)d_in[1];
    const float4* i = (const float4*)d_in[2];

    const long long total = in_sizes[0];          // B * N
    const int B = (int)(total / N_COLS);
    const long long bn = (long long)B * N_COLS;

    float* out = (float*)d_out;
    float4* z_out = (float4*)(out);               // outputs in reference order: z, v_out, i_new
    float4* v_out = (float4*)(out + bn);
    float4* i_out = (float4*)(out + 2 * bn);

    lif_wta_kernel<<<B / ROWS_PER_CTA, THREADS>>>(x, v, i, z_out, v_out, i_out);
}